// round 15
// baseline (speedup 1.0000x reference)
#include <cuda_runtime.h>
#include <cstdint>

#define N_BATCH 4
#define PTILE 128
#define NTILES 32                 /* 4096/128 */
#define CELLS 528                 /* upper-triangle tile pairs */
#define TOTALB (CELLS*N_BATCH)
#define BLOCK 128
#define FSTR 136                  /* smem row stride (floats); %32==8 -> conflict-free */
#define SLOTS 20                  /* rows: 0-14 D (A-layout), 15 h, 16-19 G */

// Precomputed slot tiles: [n][tile][20 rows][128 points]
__device__ float g_slots[N_BATCH * NTILES * SLOTS * PTILE];
__device__ double g_acc;
__device__ unsigned int g_done;

__device__ __forceinline__ float ex2f(float a) {
    float r; asm("ex2.approx.ftz.f32 %0, %1;" : "=f"(r) : "f"(a)); return r;
}
__device__ __forceinline__ float tf32r(float v) {
    uint32_t u; asm("cvt.rna.tf32.f32 %0, %1;" : "=r"(u) : "f"(v));
    return __uint_as_float(u);
}
__device__ __forceinline__ void mma8(float& d0, float& d1, float& d2, float& d3,
                                     uint32_t a0, uint32_t a1, uint32_t a2, uint32_t a3,
                                     uint32_t b0, uint32_t b1) {
    asm("mma.sync.aligned.m16n8k8.row.col.f32.tf32.tf32.f32 "
        "{%0,%1,%2,%3}, {%4,%5,%6,%7}, {%8,%9}, {%0,%1,%2,%3};"
        : "+f"(d0), "+f"(d1), "+f"(d2), "+f"(d3)
        : "r"(a0), "r"(a1), "r"(a2), "r"(a3), "r"(b0), "r"(b1));
}

// 2 threads per point: role 0 = features (rows 0-15), role 1 = seg pooling (rows 16-19).
__global__ void __launch_bounds__(128) prep_kernel(const float* __restrict__ images,
                                                   const float* __restrict__ segs) {
    const float SQL2E = 1.2011224087864498f;   // sqrt(log2 e)
    int gid  = blockIdx.x * 128 + threadIdx.x;  // 0 .. 32767
    int pt   = gid >> 1;
    int role = gid & 1;
    int n    = pt >> 12;
    int p    = pt & 4095;
    int tile = p >> 7;
    int idx  = p & 127;
    int y = p >> 6, x = p & 63;
    int ro = (y << 8) + (x << 1);

    float* o = g_slots + (size_t)(n * NTILES + tile) * SLOTS * PTILE;

    if (role == 0) {
        const float* img = images + (size_t)n * 3 * 16384;
        float f[5];
        f[0] = (float)x * (SQL2E / 50.0f);
        f[1] = (float)y * (SQL2E / 50.0f);
        f[2] = img[ro]         * (SQL2E / 15.0f);
        f[3] = img[16384 + ro] * (SQL2E / 15.0f);
        f[4] = img[32768 + ro] * (SQL2E / 15.0f);
        float h = -0.5f * (f[0]*f[0] + f[1]*f[1] + f[2]*f[2] + f[3]*f[3] + f[4]*f[4]);
#pragma unroll
        for (int d = 0; d < 5; d++) {
            float hi = tf32r(f[d]);
            float lo = tf32r(f[d] - hi);
            o[d * PTILE + idx]        = hi;
            o[(5 + d) * PTILE + idx]  = hi;
            o[(10 + d) * PTILE + idx] = lo;
        }
        o[15 * PTILE + idx] = h;
    } else {
        const float* sg = segs + (size_t)n * 4 * 16384;
#pragma unroll
        for (int k = 0; k < 4; k++) {
            const float* sk = sg + k * 16384;
            float s = (sk[ro] + sk[ro + 1] + sk[ro + 128] + sk[ro + 129]) * 0.25f;
            o[(16 + k) * PTILE + idx] = tf32r(s);
        }
    }
}

__global__ void __launch_bounds__(BLOCK) crf_kernel(float* __restrict__ out) {
    __shared__ float sFA[SLOTS * FSTR];   // p-tile slots (A layout)
    __shared__ float sFB[SLOTS * FSTR];   // q-tile slots (B layout)
    __shared__ float sHA[PTILE];
    __shared__ float sHB[PTILE];
    __shared__ float wsum[BLOCK / 32];

    int tid  = threadIdx.x;
    int w    = tid >> 5;
    int lane = tid & 31;
    int g    = lane & 3;
    int r    = lane >> 2;
    int n = blockIdx.y;

    // decode upper-triangle cell t -> (I, J), J >= I
    int t = blockIdx.x;
    float ft = (float)t;
    int I = (int)((2.0f*NTILES + 1.0f - sqrtf((2.0f*NTILES+1.0f)*(2.0f*NTILES+1.0f) - 8.0f*ft)) * 0.5f);
    while (I * NTILES - (I * (I - 1)) / 2 > t) I--;
    while ((I + 1) * NTILES - ((I + 1) * I) / 2 <= t) I++;
    int J = I + (t - (I * NTILES - (I * (I - 1)) / 2));

    const float* srcA = g_slots + (size_t)(n * NTILES + I) * SLOTS * PTILE;
    const float* srcB = g_slots + (size_t)(n * NTILES + J) * SLOTS * PTILE;

    // ---- copy prologue: each warp copies one full slot row per step (uniform, coalesced) ----
    // B layout = A layout with slot rows 5-9 <-> 10-14 swapped (hi.lo vs lo.hi pairing).
#pragma unroll
    for (int k = 0; k < 5; k++) {
        int i4  = tid + 128 * k;     // 0..639 float4 index
        int row = i4 >> 5;
        int c4  = i4 & 31;
        float4 va = *(const float4*)&srcA[row * PTILE + c4 * 4];
        int srow = (row < 5) ? row : (row < 10) ? row + 5 : (row < 15) ? row - 5 : row;
        float4 vb = *(const float4*)&srcB[srow * PTILE + c4 * 4];
        if (row == 15) {
            *(float4*)&sHA[c4 * 4] = va;
            *(float4*)&sHB[c4 * 4] = vb;
            va = make_float4(0.f, 0.f, 0.f, 0.f);
            vb = make_float4(0.f, 0.f, 0.f, 0.f);
        }
        *(float4*)&sFA[row * FSTR + c4 * 4] = va;
        *(float4*)&sFB[row * FSTR + c4 * 4] = vb;
    }
    __syncthreads();

    // ---- per-warp: 32 p-rows (row-blocks at base, base+16), all q in 16 n-chunks ----
    int base = 32 * w;

    uint32_t A0[2][4], A1[2][4];
#pragma unroll
    for (int ks = 0; ks < 2; ks++) {
        int k0 = 8 * ks;
        A0[ks][0] = __float_as_uint(sFA[(k0 + g) * FSTR + base + r]);
        A0[ks][1] = __float_as_uint(sFA[(k0 + g) * FSTR + base + r + 8]);
        A0[ks][2] = __float_as_uint(sFA[(k0 + g + 4) * FSTR + base + r]);
        A0[ks][3] = __float_as_uint(sFA[(k0 + g + 4) * FSTR + base + r + 8]);
        A1[ks][0] = __float_as_uint(sFA[(k0 + g) * FSTR + base + 16 + r]);
        A1[ks][1] = __float_as_uint(sFA[(k0 + g) * FSTR + base + 16 + r + 8]);
        A1[ks][2] = __float_as_uint(sFA[(k0 + g + 4) * FSTR + base + 16 + r]);
        A1[ks][3] = __float_as_uint(sFA[(k0 + g + 4) * FSTR + base + 16 + r + 8]);
    }
    uint32_t GA00 = __float_as_uint(sFA[(16 + g) * FSTR + base + r]);
    uint32_t GA01 = __float_as_uint(sFA[(16 + g) * FSTR + base + r + 8]);
    uint32_t GA10 = __float_as_uint(sFA[(16 + g) * FSTR + base + 16 + r]);
    uint32_t GA11 = __float_as_uint(sFA[(16 + g) * FSTR + base + 16 + r + 8]);

    float hp0 = sHA[base + r];
    float hp1 = sHA[base + r + 8];
    float hp2 = sHA[base + 16 + r];
    float hp3 = sHA[base + 16 + r + 8];

    float ac0 = 0.f, ac1 = 0.f, ac2 = 0.f, ac3 = 0.f;

#pragma unroll 2
    for (int j = 0; j < 16; j++) {
        int n0 = 8 * j;

        // B-side fragments, shared by both row-blocks
        uint32_t b00 = __float_as_uint(sFB[(g) * FSTR + n0 + r]);
        uint32_t b01 = __float_as_uint(sFB[(g + 4) * FSTR + n0 + r]);
        uint32_t b10 = __float_as_uint(sFB[(8 + g) * FSTR + n0 + r]);
        uint32_t b11 = __float_as_uint(sFB[(12 + g) * FSTR + n0 + r]);
        uint32_t gb  = __float_as_uint(sFB[(16 + g) * FSTR + n0 + r]);
        float2 hq = *(const float2*)&sHB[n0 + 2 * g];

        // row-block 0
        {
            float d0 = hp0 + hq.x, d1 = hp0 + hq.y, d2 = hp1 + hq.x, d3 = hp1 + hq.y;
            mma8(d0, d1, d2, d3, A0[0][0], A0[0][1], A0[0][2], A0[0][3], b00, b01);
            mma8(d0, d1, d2, d3, A0[1][0], A0[1][1], A0[1][2], A0[1][3], b10, b11);
            float g0 = 0.f, g1 = 0.f, g2 = 0.f, g3 = 0.f;
            mma8(g0, g1, g2, g3, GA00, GA01, 0u, 0u, gb, 0u);
            ac0 = fmaf(ex2f(d0), g0, ac0);
            ac1 = fmaf(ex2f(d1), g1, ac1);
            ac0 = fmaf(ex2f(d2), g2, ac0);
            ac1 = fmaf(ex2f(d3), g3, ac1);
        }
        // row-block 1 (same B fragments)
        {
            float d0 = hp2 + hq.x, d1 = hp2 + hq.y, d2 = hp3 + hq.x, d3 = hp3 + hq.y;
            mma8(d0, d1, d2, d3, A1[0][0], A1[0][1], A1[0][2], A1[0][3], b00, b01);
            mma8(d0, d1, d2, d3, A1[1][0], A1[1][1], A1[1][2], A1[1][3], b10, b11);
            float g0 = 0.f, g1 = 0.f, g2 = 0.f, g3 = 0.f;
            mma8(g0, g1, g2, g3, GA10, GA11, 0u, 0u, gb, 0u);
            ac2 = fmaf(ex2f(d0), g0, ac2);
            ac3 = fmaf(ex2f(d1), g1, ac3);
            ac2 = fmaf(ex2f(d2), g2, ac2);
            ac3 = fmaf(ex2f(d3), g3, ac3);
        }
    }

    float acc = (ac0 + ac1) + (ac2 + ac3);
    if (I != J) acc *= 2.0f;   // symmetric off-diagonal cell

    // warp + block reduce, one double atomic per block
#pragma unroll
    for (int off = 16; off > 0; off >>= 1)
        acc += __shfl_down_sync(0xFFFFFFFFu, acc, off);
    if (lane == 0) wsum[w] = acc;
    __syncthreads();
    if (tid == 0) {
        float s = (wsum[0] + wsum[1]) + (wsum[2] + wsum[3]);
        atomicAdd(&g_acc, (double)s);
        __threadfence();
        unsigned int d = atomicAdd(&g_done, 1u);
        if (d == TOTALB - 1u) {
            double total = *((volatile double*)&g_acc);
            out[0] = (float)(total * (-1e-7 / (double)N_BATCH));
            g_acc = 0.0;          // reset for next graph replay
            g_done = 0u;
        }
    }
}

extern "C" void kernel_launch(void* const* d_in, const int* in_sizes, int n_in,
                              void* d_out, int out_size) {
    const float* images = (const float*)d_in[0];
    const float* segs   = (const float*)d_in[1];

    prep_kernel<<<256, 128>>>(images, segs);

    dim3 grid(CELLS, N_BATCH);
    crf_kernel<<<grid, BLOCK>>>((float*)d_out);
}

// round 16
// speedup vs baseline: 1.0101x; 1.0101x over previous
#include <cuda_runtime.h>
#include <cstdint>

#define N_BATCH 4
#define PTILE 128
#define NTILES 32
#define CELLS 528                 /* upper-triangle tile pairs */
#define TOTALB (CELLS*N_BATCH)
#define BLOCK 128
#define FSTR 136                  /* A smem row stride, conflict-free */
#define B2STR 132                 /* B pair-row stride in float2 (pad 4) */
#define GSTR 136

/* global slot store per (n,tile): 
   [0..2559]    A-part: rows 0-14 D(A-layout), 15 h, 16-19 G   (20 x 128)
   [2560..4607] B pairs: float2[8][128]  row pr={B[8ks+g],B[8ks+g+4]}
   [4608..5119] B G rows: [4][128]
   [5120..5247] B h row  : [128]                                       */
#define TSTRIDE 5248
#define B2_OFF 2560
#define BG_OFF 4608
#define BH_OFF 5120

__device__ float g_slots[N_BATCH * NTILES * TSTRIDE];
__device__ double g_acc;
__device__ unsigned int g_done;

__device__ __forceinline__ float ex2f(float a) {
    float r; asm("ex2.approx.ftz.f32 %0, %1;" : "=f"(r) : "f"(a)); return r;
}
__device__ __forceinline__ float tf32r(float v) {
    uint32_t u; asm("cvt.rna.tf32.f32 %0, %1;" : "=r"(u) : "f"(v));
    return __uint_as_float(u);
}
__device__ __forceinline__ void mma8(float& d0, float& d1, float& d2, float& d3,
                                     uint32_t a0, uint32_t a1, uint32_t a2, uint32_t a3,
                                     uint32_t b0, uint32_t b1) {
    asm("mma.sync.aligned.m16n8k8.row.col.f32.tf32.tf32.f32 "
        "{%0,%1,%2,%3}, {%4,%5,%6,%7}, {%8,%9}, {%0,%1,%2,%3};"
        : "+f"(d0), "+f"(d1), "+f"(d2), "+f"(d3)
        : "r"(a0), "r"(a1), "r"(a2), "r"(a3), "r"(b0), "r"(b1));
}

// 2 threads per point: role 0 = features, role 1 = seg pooling.
__global__ void __launch_bounds__(128) prep_kernel(const float* __restrict__ images,
                                                   const float* __restrict__ segs) {
    const float SQL2E = 1.2011224087864498f;
    int gid  = blockIdx.x * 128 + threadIdx.x;   // 0..32767
    int pt   = gid >> 1;
    int role = gid & 1;
    int n    = pt >> 12;
    int p    = pt & 4095;
    int tile = p >> 7;
    int idx  = p & 127;
    int y = p >> 6, x = p & 63;
    int ro = (y << 8) + (x << 1);

    float* o = g_slots + (size_t)(n * NTILES + tile) * TSTRIDE;

    if (role == 0) {
        const float* img = images + (size_t)n * 3 * 16384;
        float f[5];
        f[0] = (float)x * (SQL2E / 50.0f);
        f[1] = (float)y * (SQL2E / 50.0f);
        f[2] = img[ro]         * (SQL2E / 15.0f);
        f[3] = img[16384 + ro] * (SQL2E / 15.0f);
        f[4] = img[32768 + ro] * (SQL2E / 15.0f);
        float h = -0.5f * (f[0]*f[0] + f[1]*f[1] + f[2]*f[2] + f[3]*f[3] + f[4]*f[4]);
        float hi[5], lo[5];
#pragma unroll
        for (int d = 0; d < 5; d++) {
            hi[d] = tf32r(f[d]);
            lo[d] = tf32r(f[d] - hi[d]);
            o[d * PTILE + idx]        = hi[d];
            o[(5 + d) * PTILE + idx]  = hi[d];
            o[(10 + d) * PTILE + idx] = lo[d];
        }
        o[15 * PTILE + idx] = h;
        // B pair rows: pr=4ks+g holds {Bslot[8ks+g], Bslot[8ks+g+4]}
        // B slots: 0-4 hi, 5-9 lo, 10-14 hi(dup), 15 zero
        float2* b2 = (float2*)(o + B2_OFF);
        b2[0 * PTILE + idx] = make_float2(hi[0], hi[4]);
        b2[1 * PTILE + idx] = make_float2(hi[1], lo[0]);
        b2[2 * PTILE + idx] = make_float2(hi[2], lo[1]);
        b2[3 * PTILE + idx] = make_float2(hi[3], lo[2]);
        b2[4 * PTILE + idx] = make_float2(lo[3], hi[2]);
        b2[5 * PTILE + idx] = make_float2(lo[4], hi[3]);
        b2[6 * PTILE + idx] = make_float2(hi[0], hi[4]);
        b2[7 * PTILE + idx] = make_float2(hi[1], 0.0f);
        o[BH_OFF + idx] = h;
    } else {
        const float* sg = segs + (size_t)n * 4 * 16384;
#pragma unroll
        for (int k = 0; k < 4; k++) {
            const float* sk = sg + k * 16384;
            float s = tf32r((sk[ro] + sk[ro + 1] + sk[ro + 128] + sk[ro + 129]) * 0.25f);
            o[(16 + k) * PTILE + idx] = s;   // A G rows
            o[BG_OFF + k * PTILE + idx] = s; // B G rows
        }
    }
}

__global__ void __launch_bounds__(BLOCK) crf_kernel(float* __restrict__ out) {
    __shared__ float  sFA[20 * FSTR];    // A slots (rows 0-14 D, 15 zero, 16-19 G)
    __shared__ float  sHA[PTILE];
    __shared__ float2 sB2[8 * B2STR];    // B pair rows, padded
    __shared__ float  sBG[4 * GSTR];
    __shared__ float  sBH[PTILE];
    __shared__ float  wsum[BLOCK / 32];

    int tid  = threadIdx.x;
    int w    = tid >> 5;
    int lane = tid & 31;
    int g    = lane & 3;
    int r    = lane >> 2;
    int n = blockIdx.y;

    // decode upper-triangle cell t -> (I, J), J >= I
    int t = blockIdx.x;
    float ft = (float)t;
    int I = (int)((2.0f*NTILES + 1.0f - sqrtf((2.0f*NTILES+1.0f)*(2.0f*NTILES+1.0f) - 8.0f*ft)) * 0.5f);
    while (I * NTILES - (I * (I - 1)) / 2 > t) I--;
    while ((I + 1) * NTILES - ((I + 1) * I) / 2 <= t) I++;
    int J = I + (t - (I * NTILES - (I * (I - 1)) / 2));

    const float* srcA = g_slots + (size_t)(n * NTILES + I) * TSTRIDE;
    const float* srcB = g_slots + (size_t)(n * NTILES + J) * TSTRIDE;

    // ---- A copy: 20 rows x 128, float4 (row 15 = h -> sHA, zero in sFA) ----
#pragma unroll
    for (int k = 0; k < 5; k++) {
        int i4  = tid + 128 * k;
        int row = i4 >> 5;
        int c4  = i4 & 31;
        float4 v = *(const float4*)&srcA[row * PTILE + c4 * 4];
        if (row == 15) {
            *(float4*)&sHA[c4 * 4] = v;
            v = make_float4(0.f, 0.f, 0.f, 0.f);
        }
        *(float4*)&sFA[row * FSTR + c4 * 4] = v;
    }
    // ---- B pair copy: 8 rows x 128 float2 = 512 float4 ----
#pragma unroll
    for (int k = 0; k < 4; k++) {
        int i4  = tid + 128 * k;
        int row = i4 >> 6;
        int c4  = i4 & 63;          // pairs of float2
        float4 v = *(const float4*)&srcB[B2_OFF + row * 256 + c4 * 4];
        *(float4*)&sB2[row * B2STR + c4 * 2] = v;
    }
    // ---- B G copy: 4 rows x 128 = 128 float4 ----
    {
        int row = tid >> 5;
        int c4  = tid & 31;
        float4 v = *(const float4*)&srcB[BG_OFF + row * PTILE + c4 * 4];
        *(float4*)&sBG[row * GSTR + c4 * 4] = v;
    }
    sBH[tid] = srcB[BH_OFF + tid];
    __syncthreads();

    // ---- per-warp: 32 p-rows (row-blocks base, base+16), 16 n-chunks ----
    int base = 32 * w;

    uint32_t A0[2][4], A1[2][4];
#pragma unroll
    for (int ks = 0; ks < 2; ks++) {
        int k0 = 8 * ks;
        A0[ks][0] = __float_as_uint(sFA[(k0 + g) * FSTR + base + r]);
        A0[ks][1] = __float_as_uint(sFA[(k0 + g) * FSTR + base + r + 8]);
        A0[ks][2] = __float_as_uint(sFA[(k0 + g + 4) * FSTR + base + r]);
        A0[ks][3] = __float_as_uint(sFA[(k0 + g + 4) * FSTR + base + r + 8]);
        A1[ks][0] = __float_as_uint(sFA[(k0 + g) * FSTR + base + 16 + r]);
        A1[ks][1] = __float_as_uint(sFA[(k0 + g) * FSTR + base + 16 + r + 8]);
        A1[ks][2] = __float_as_uint(sFA[(k0 + g + 4) * FSTR + base + 16 + r]);
        A1[ks][3] = __float_as_uint(sFA[(k0 + g + 4) * FSTR + base + 16 + r + 8]);
    }
    uint32_t GA00 = __float_as_uint(sFA[(16 + g) * FSTR + base + r]);
    uint32_t GA01 = __float_as_uint(sFA[(16 + g) * FSTR + base + r + 8]);
    uint32_t GA10 = __float_as_uint(sFA[(16 + g) * FSTR + base + 16 + r]);
    uint32_t GA11 = __float_as_uint(sFA[(16 + g) * FSTR + base + 16 + r + 8]);

    float hp0 = sHA[base + r];
    float hp1 = sHA[base + r + 8];
    float hp2 = sHA[base + 16 + r];
    float hp3 = sHA[base + 16 + r + 8];

    const float2* pB0 = sB2 + g * B2STR + r;
    const float2* pB1 = sB2 + (4 + g) * B2STR + r;
    const float*  pG  = sBG + g * GSTR + r;
    const float*  pH  = sBH + 2 * g;

    float ac0 = 0.f, ac1 = 0.f, ac2 = 0.f, ac3 = 0.f;

#pragma unroll 4
    for (int j = 0; j < 16; j++) {
        int n0 = 8 * j;

        float2 fb0 = pB0[n0];
        float2 fb1 = pB1[n0];
        uint32_t b00 = __float_as_uint(fb0.x), b01 = __float_as_uint(fb0.y);
        uint32_t b10 = __float_as_uint(fb1.x), b11 = __float_as_uint(fb1.y);
        uint32_t gb  = __float_as_uint(pG[n0]);
        float2 hq = *(const float2*)&pH[n0];

        // row-block 0
        {
            float d0 = hp0 + hq.x, d1 = hp0 + hq.y, d2 = hp1 + hq.x, d3 = hp1 + hq.y;
            mma8(d0, d1, d2, d3, A0[0][0], A0[0][1], A0[0][2], A0[0][3], b00, b01);
            mma8(d0, d1, d2, d3, A0[1][0], A0[1][1], A0[1][2], A0[1][3], b10, b11);
            float g0 = 0.f, g1 = 0.f, g2 = 0.f, g3 = 0.f;
            mma8(g0, g1, g2, g3, GA00, GA01, 0u, 0u, gb, 0u);
            ac0 = fmaf(ex2f(d0), g0, ac0);
            ac1 = fmaf(ex2f(d1), g1, ac1);
            ac0 = fmaf(ex2f(d2), g2, ac0);
            ac1 = fmaf(ex2f(d3), g3, ac1);
        }
        // row-block 1 (same B fragments)
        {
            float d0 = hp2 + hq.x, d1 = hp2 + hq.y, d2 = hp3 + hq.x, d3 = hp3 + hq.y;
            mma8(d0, d1, d2, d3, A1[0][0], A1[0][1], A1[0][2], A1[0][3], b00, b01);
            mma8(d0, d1, d2, d3, A1[1][0], A1[1][1], A1[1][2], A1[1][3], b10, b11);
            float g0 = 0.f, g1 = 0.f, g2 = 0.f, g3 = 0.f;
            mma8(g0, g1, g2, g3, GA10, GA11, 0u, 0u, gb, 0u);
            ac2 = fmaf(ex2f(d0), g0, ac2);
            ac3 = fmaf(ex2f(d1), g1, ac3);
            ac2 = fmaf(ex2f(d2), g2, ac2);
            ac3 = fmaf(ex2f(d3), g3, ac3);
        }
    }

    float acc = (ac0 + ac1) + (ac2 + ac3);
    if (I != J) acc *= 2.0f;

    // warp + block reduce, one double atomic per block
#pragma unroll
    for (int off = 16; off > 0; off >>= 1)
        acc += __shfl_down_sync(0xFFFFFFFFu, acc, off);
    if (lane == 0) wsum[w] = acc;
    __syncthreads();
    if (tid == 0) {
        float s = (wsum[0] + wsum[1]) + (wsum[2] + wsum[3]);
        atomicAdd(&g_acc, (double)s);
        __threadfence();
        unsigned int d = atomicAdd(&g_done, 1u);
        if (d == TOTALB - 1u) {
            double total = *((volatile double*)&g_acc);
            out[0] = (float)(total * (-1e-7 / (double)N_BATCH));
            g_acc = 0.0;          // reset for next graph replay
            g_done = 0u;
        }
    }
}

extern "C" void kernel_launch(void* const* d_in, const int* in_sizes, int n_in,
                              void* d_out, int out_size) {
    const float* images = (const float*)d_in[0];
    const float* segs   = (const float*)d_in[1];

    prep_kernel<<<256, 128>>>(images, segs);

    dim3 grid(CELLS, N_BATCH);
    crf_kernel<<<grid, BLOCK>>>((float*)d_out);
}